// round 2
// baseline (speedup 1.0000x reference)
#include <cuda_runtime.h>

#define NCAMS 6
#define CFEAT 64
#define HH 88
#define WW 160
#define HWSZ (HH*WW)
#define NVOX 200000
#define TILE 32

__global__ __launch_bounds__(256, 1) void vox_fusion_kernel(
    const float* __restrict__ feat,    // [6,64,88,160]
    const float* __restrict__ maskp,   // [6,1,88,160]
    const float* __restrict__ Kmat,    // [6,4,4]
    const float* __restrict__ extp,    // [6,4,4]
    const float* __restrict__ w_no,    // [64,65]
    const float* __restrict__ b_no,    // [64]
    const float* __restrict__ w_o,     // [64,130]
    const float* __restrict__ b_o,     // [64]
    float* __restrict__ out)           // [64, 200000]
{
    __shared__ float sE[NCAMS][12];    // extrinsics rows 0..2 (3x4)
    __shared__ float sK[NCAMS][9];     // K 3x3
    __shared__ float sf1[TILE * 65];   // group {0,3,4} accumulated features
    __shared__ float sf2[TILE * 65];   // group {1,2,5}
    __shared__ int   scnt[TILE];

    const int t = threadIdx.x;
    if (t < NCAMS * 12) {
        int cam = t / 12, e = t % 12;
        sE[cam][e] = extp[cam * 16 + e];
    } else if (t < NCAMS * 12 + NCAMS * 9) {
        int u = t - NCAMS * 12;
        int cam = u / 9, e = u % 9;
        sK[cam][e] = Kmat[cam * 16 + (e / 3) * 4 + (e % 3)];
    }
    __syncthreads();

    const int i = t & 31;      // voxel within tile
    const int j = t >> 5;      // channel group 0..7 (channels j*8 .. j*8+7)
    const int n = blockIdx.x * TILE + i;

    const int ixv = n % 100;
    const int iyv = (n / 100) % 100;
    const int izv = n / 10000;
    const float px = -50.0f + (float)ixv;
    const float py = -50.0f + (float)iyv;
    const float pz = -15.0f + 1.5f * (float)izv;

    float acc1[8], acc2[8];
#pragma unroll
    for (int k = 0; k < 8; k++) { acc1[k] = 0.0f; acc2[k] = 0.0f; }
    float z1 = 0.0f, z2 = 0.0f;
    int cnt = 0;

#pragma unroll
    for (int cam = 0; cam < NCAMS; cam++) {
        const float* E  = sE[cam];
        const float* Km = sK[cam];
        // v_local = ext[:3,:] @ (px,py,pz,1)
        float vx = fmaf(E[0], px, fmaf(E[1], py, fmaf(E[2],  pz, E[3])));
        float vy = fmaf(E[4], px, fmaf(E[5], py, fmaf(E[6],  pz, E[7])));
        float vz = fmaf(E[8], px, fmaf(E[9], py, fmaf(E[10], pz, E[11])));
        // cam_pts = K3 @ v_local
        float cx = fmaf(Km[0], vx, fmaf(Km[1], vy, Km[2] * vz));
        float cy = fmaf(Km[3], vx, fmaf(Km[4], vy, Km[5] * vz));
        float cz = fmaf(Km[6], vx, fmaf(Km[7], vy, Km[8] * vz));
        float denom = cz + 1e-8f;
        float pixx = cx / denom;
        float pixy = cy / denom;
        float gx = (pixx / 159.0f - 0.5f) * 2.0f;
        float gy = (pixy / 87.0f  - 0.5f) * 2.0f;
        bool oob = (gx > 1.0f) || (gx < -1.0f) || (gy > 1.0f) || (gy < -1.0f);
        float x = (gx + 1.0f) * 0.5f * 159.0f;
        float y = (gy + 1.0f) * 0.5f * 87.0f;
        // nearest mask sample (round-half-even, zeros padding)
        float xr = rintf(x), yr = rintf(y);
        float mv = 0.0f;
        if (xr >= 0.0f && xr <= 159.0f && yr >= 0.0f && yr <= 87.0f) {
            mv = __ldg(&maskp[cam * HWSZ + (int)yr * WW + (int)xr]);
        }
        bool valid = (mv > 0.5f) && (vz > 0.0f) && (!oob);
        if (valid) {
            cnt++;
            float x0 = floorf(x), y0 = floorf(y);
            float wx1 = x - x0, wx0 = 1.0f - wx1;
            float wy1 = y - y0, wy0 = 1.0f - wy1;
            float xs2[2] = {x0, x0 + 1.0f}, wxa[2] = {wx0, wx1};
            float ys2[2] = {y0, y0 + 1.0f}, wya[2] = {wy0, wy1};
            float cw[4]; int off[4];
            int idx = 0;
#pragma unroll
            for (int a = 0; a < 2; a++) {
#pragma unroll
                for (int b = 0; b < 2; b++) {
                    float xi = xs2[a], yi = ys2[b];
                    bool v = (xi >= 0.0f) && (xi <= 159.0f) && (yi >= 0.0f) && (yi <= 87.0f);
                    float xc = fminf(fmaxf(xi, 0.0f), 159.0f);
                    float yc = fminf(fmaxf(yi, 0.0f), 87.0f);
                    off[idx] = (int)yc * WW + (int)xc;
                    cw[idx]  = wxa[a] * wya[b] * (v ? 1.0f : 0.0f);
                    idx++;
                }
            }
            const float* base = feat + cam * (CFEAT * HWSZ) + (j * 8) * HWSZ;
            bool g1 = (cam == 0) || (cam == 3) || (cam == 4);
#pragma unroll
            for (int k = 0; k < 8; k++) {
                const float* bk = base + k * HWSZ;
                float v0 = __ldg(bk + off[0]);
                float v1 = __ldg(bk + off[1]);
                float v2 = __ldg(bk + off[2]);
                float v3 = __ldg(bk + off[3]);
                float val = fmaf(v3, cw[3], fmaf(v2, cw[2], fmaf(v1, cw[1], v0 * cw[0])));
                if (g1) acc1[k] += val; else acc2[k] += val;
            }
            float zc = vz / 100.0f;
            if (g1) z1 += zc; else z2 += zc;
        }
    }

#pragma unroll
    for (int k = 0; k < 8; k++) {
        sf1[i * 65 + j * 8 + k] = acc1[k];
        sf2[i * 65 + j * 8 + k] = acc2[k];
    }
    if (j == 0) {
        sf1[i * 65 + 64] = z1;
        sf2[i * 65 + 64] = z2;
        scnt[i] = cnt;
    }
    __syncthreads();

    // Phase 2: per-voxel linear + ELU. Thread handles voxel i, outputs j*8..j*8+7.
    const int cv = scnt[i];
#pragma unroll
    for (int m = 0; m < 8; m++) {
        int o = j * 8 + m;
        float r = 0.0f;
        if (cv == 1) {
            float s = __ldg(&b_no[o]);
            const float* w = w_no + o * 65;
#pragma unroll 5
            for (int k = 0; k < 65; k++)
                s = fmaf(__ldg(&w[k]), sf1[i * 65 + k] + sf2[i * 65 + k], s);
            r = (s > 0.0f) ? s : expm1f(s);
        } else if (cv == 2) {
            float s = __ldg(&b_o[o]);
            const float* w = w_o + o * 130;
#pragma unroll 5
            for (int k = 0; k < 65; k++)
                s = fmaf(__ldg(&w[k]), sf1[i * 65 + k], s);
#pragma unroll 5
            for (int k = 0; k < 65; k++)
                s = fmaf(__ldg(&w[65 + k]), sf2[i * 65 + k], s);
            r = (s > 0.0f) ? s : expm1f(s);
        }
        out[o * NVOX + n] = r;
    }
}

extern "C" void kernel_launch(void* const* d_in, const int* in_sizes, int n_in,
                              void* d_out, int out_size) {
    const float* feat  = (const float*)d_in[0];
    const float* maskp = (const float*)d_in[1];
    const float* Kmat  = (const float*)d_in[2];
    const float* extp  = (const float*)d_in[3];
    const float* w_no  = (const float*)d_in[4];
    const float* b_no  = (const float*)d_in[5];
    const float* w_o   = (const float*)d_in[6];
    const float* b_o   = (const float*)d_in[7];
    float* out = (float*)d_out;
    vox_fusion_kernel<<<NVOX / TILE, 256>>>(feat, maskp, Kmat, extp,
                                            w_no, b_no, w_o, b_o, out);
}

// round 3
// speedup vs baseline: 2.1420x; 2.1420x over previous
#include <cuda_runtime.h>

#define NCAMS 6
#define CFEAT 64
#define HH 88
#define WW 160
#define HWSZ (HH*WW)
#define NVOX 200000
#define TILE 32

__global__ __launch_bounds__(256) void vox_fusion_kernel(
    const float* __restrict__ feat,    // [6,64,88,160]
    const float* __restrict__ maskp,   // [6,1,88,160]
    const float* __restrict__ Kmat,    // [6,4,4]
    const float* __restrict__ extp,    // [6,4,4]
    const float* __restrict__ w_no,    // [64,65]
    const float* __restrict__ b_no,    // [64]
    const float* __restrict__ w_o,     // [64,130]
    const float* __restrict__ b_o,     // [64]
    float* __restrict__ out)           // [64, 200000]
{
    __shared__ float sE[NCAMS][12];
    __shared__ float sK[NCAMS][9];
    __shared__ unsigned svalid[NCAMS];      // bit i = voxel i valid for cam
    __shared__ float4 scw[NCAMS * TILE];    // bilinear corner weights per pair
    __shared__ int4   soff[NCAMS * TILE];   // corner offsets per pair
    __shared__ float  svz[NCAMS * TILE];    // vz/100 (0 if invalid)
    __shared__ float  sf1[TILE * 65];       // group {0,3,4}
    __shared__ float  sf2[TILE * 65];       // group {1,2,5}
    __shared__ float  swno[CFEAT * 65];     // staged w_no
    __shared__ float  sbno[CFEAT];

    const int t = threadIdx.x;

    // stage camera matrices
    if (t < 72) {
        sE[t / 12][t % 12] = extp[(t / 12) * 16 + (t % 12)];
    } else if (t < 126) {
        int u = t - 72; int cam = u / 9, e = u % 9;
        sK[cam][e] = Kmat[cam * 16 + (e / 3) * 4 + (e % 3)];
    }
    // stage w_no / b_no (coalesced)
    for (int idx = t; idx < CFEAT * 65; idx += 256) swno[idx] = w_no[idx];
    if (t < CFEAT) sbno[t] = b_no[t];
    __syncthreads();

    const int i = t & 31;                   // voxel within tile
    const int n = blockIdx.x * TILE + i;

    // ---- Phase 0: projection + validity, one thread per (voxel, cam) ----
    if (t < 192) {
        const int cam = t >> 5;
        const int ixv = n % 100;
        const int iyv = (n / 100) % 100;
        const int izv = n / 10000;
        const float px = -50.0f + (float)ixv;
        const float py = -50.0f + (float)iyv;
        const float pz = -15.0f + 1.5f * (float)izv;

        const float* E  = sE[cam];
        const float* Km = sK[cam];
        float vx = fmaf(E[0], px, fmaf(E[1], py, fmaf(E[2],  pz, E[3])));
        float vy = fmaf(E[4], px, fmaf(E[5], py, fmaf(E[6],  pz, E[7])));
        float vz = fmaf(E[8], px, fmaf(E[9], py, fmaf(E[10], pz, E[11])));
        float cx = fmaf(Km[0], vx, fmaf(Km[1], vy, Km[2] * vz));
        float cy = fmaf(Km[3], vx, fmaf(Km[4], vy, Km[5] * vz));
        float cz = fmaf(Km[6], vx, fmaf(Km[7], vy, Km[8] * vz));
        float denom = cz + 1e-8f;
        float pixx = cx / denom;
        float pixy = cy / denom;
        float gx = (pixx / 159.0f - 0.5f) * 2.0f;
        float gy = (pixy / 87.0f  - 0.5f) * 2.0f;
        bool oob = (gx > 1.0f) || (gx < -1.0f) || (gy > 1.0f) || (gy < -1.0f);
        float x = (gx + 1.0f) * 0.5f * 159.0f;
        float y = (gy + 1.0f) * 0.5f * 87.0f;
        float xr = rintf(x), yr = rintf(y);
        float mv = 0.0f;
        if (xr >= 0.0f && xr <= 159.0f && yr >= 0.0f && yr <= 87.0f)
            mv = __ldg(&maskp[cam * HWSZ + (int)yr * WW + (int)xr]);
        bool valid = (mv > 0.5f) && (vz > 0.0f) && (!oob);

        float4 cw4 = make_float4(0.f, 0.f, 0.f, 0.f);
        int4   o4  = make_int4(0, 0, 0, 0);
        float  vzc = 0.0f;
        if (valid) {
            float x0 = floorf(x), y0 = floorf(y);
            float wx1 = x - x0, wx0 = 1.0f - wx1;
            float wy1 = y - y0, wy0 = 1.0f - wy1;
            float xs2[2] = {x0, x0 + 1.0f}, wxa[2] = {wx0, wx1};
            float ys2[2] = {y0, y0 + 1.0f}, wya[2] = {wy0, wy1};
            float cw[4]; int off[4];
            int idx = 0;
#pragma unroll
            for (int a = 0; a < 2; a++) {
#pragma unroll
                for (int b = 0; b < 2; b++) {
                    float xi = xs2[a], yi = ys2[b];
                    bool v = (xi >= 0.0f) && (xi <= 159.0f) && (yi >= 0.0f) && (yi <= 87.0f);
                    float xc = fminf(fmaxf(xi, 0.0f), 159.0f);
                    float yc = fminf(fmaxf(yi, 0.0f), 87.0f);
                    off[idx] = (int)yc * WW + (int)xc;
                    cw[idx]  = wxa[a] * wya[b] * (v ? 1.0f : 0.0f);
                    idx++;
                }
            }
            cw4 = make_float4(cw[0], cw[1], cw[2], cw[3]);
            o4  = make_int4(off[0], off[1], off[2], off[3]);
            vzc = vz * 0.01f;
        }
        unsigned bal = __ballot_sync(0xffffffffu, valid);
        if (i == 0) svalid[cam] = bal;
        scw[t]  = cw4;
        soff[t] = o4;
        svz[t]  = vzc;
    }
    __syncthreads();

    // ---- Phase 1: gather only for voxels with count 1 or 2 ----
    const int j = t >> 5;                   // channel group 0..7
    int cnt = 0;
#pragma unroll
    for (int c = 0; c < NCAMS; c++) cnt += (svalid[c] >> i) & 1;
    const bool active = (cnt == 1) || (cnt == 2);

    if (active) {
        float acc1[8], acc2[8];
#pragma unroll
        for (int k = 0; k < 8; k++) { acc1[k] = 0.0f; acc2[k] = 0.0f; }
#pragma unroll
        for (int cam = 0; cam < NCAMS; cam++) {
            if ((svalid[cam] >> i) & 1) {
                float4 w4 = scw[cam * TILE + i];
                int4   o4 = soff[cam * TILE + i];
                const float* base = feat + cam * (CFEAT * HWSZ) + (j * 8) * HWSZ;
                const bool g1 = (cam == 0) || (cam == 3) || (cam == 4);
#pragma unroll
                for (int k = 0; k < 8; k++) {
                    const float* bk = base + k * HWSZ;
                    float v0 = __ldg(bk + o4.x);
                    float v1 = __ldg(bk + o4.y);
                    float v2 = __ldg(bk + o4.z);
                    float v3 = __ldg(bk + o4.w);
                    float val = fmaf(v3, w4.w, fmaf(v2, w4.z, fmaf(v1, w4.y, v0 * w4.x)));
                    if (g1) acc1[k] += val; else acc2[k] += val;
                }
            }
        }
#pragma unroll
        for (int k = 0; k < 8; k++) {
            sf1[i * 65 + j * 8 + k] = acc1[k];
            sf2[i * 65 + j * 8 + k] = acc2[k];
        }
        if (j == 0) {
            sf1[i * 65 + 64] = svz[0 * TILE + i] + svz[3 * TILE + i] + svz[4 * TILE + i];
            sf2[i * 65 + 64] = svz[1 * TILE + i] + svz[2 * TILE + i] + svz[5 * TILE + i];
        }
    }
    __syncthreads();

    // ---- Phase 2: per-voxel linear + ELU (k-outer, 8 register accumulators) ----
    float s[8];
#pragma unroll
    for (int m = 0; m < 8; m++) s[m] = 0.0f;

    unsigned anyb = __ballot_sync(0xffffffffu, active);
    if (anyb) {
        if (cnt == 1) {
            const float* w = swno + (j * 8) * 65;
#pragma unroll
            for (int m = 0; m < 8; m++) s[m] = sbno[j * 8 + m];
            for (int k = 0; k < 65; k++) {
                float f = sf1[i * 65 + k] + sf2[i * 65 + k];
#pragma unroll
                for (int m = 0; m < 8; m++)
                    s[m] = fmaf(w[m * 65 + k], f, s[m]);
            }
#pragma unroll
            for (int m = 0; m < 8; m++) s[m] = (s[m] > 0.0f) ? s[m] : expm1f(s[m]);
        } else if (cnt == 2) {
            const float* w = w_o + (j * 8) * 130;
#pragma unroll
            for (int m = 0; m < 8; m++) s[m] = __ldg(&b_o[j * 8 + m]);
            for (int k = 0; k < 65; k++) {
                float f1 = sf1[i * 65 + k];
                float f2 = sf2[i * 65 + k];
#pragma unroll
                for (int m = 0; m < 8; m++) {
                    s[m] = fmaf(__ldg(&w[m * 130 + k]), f1, s[m]);
                    s[m] = fmaf(__ldg(&w[m * 130 + 65 + k]), f2, s[m]);
                }
            }
#pragma unroll
            for (int m = 0; m < 8; m++) s[m] = (s[m] > 0.0f) ? s[m] : expm1f(s[m]);
        }
    }
#pragma unroll
    for (int m = 0; m < 8; m++)
        out[(j * 8 + m) * NVOX + n] = s[m];
}

extern "C" void kernel_launch(void* const* d_in, const int* in_sizes, int n_in,
                              void* d_out, int out_size) {
    const float* feat  = (const float*)d_in[0];
    const float* maskp = (const float*)d_in[1];
    const float* Kmat  = (const float*)d_in[2];
    const float* extp  = (const float*)d_in[3];
    const float* w_no  = (const float*)d_in[4];
    const float* b_no  = (const float*)d_in[5];
    const float* w_o   = (const float*)d_in[6];
    const float* b_o   = (const float*)d_in[7];
    float* out = (float*)d_out;
    vox_fusion_kernel<<<NVOX / TILE, 256>>>(feat, maskp, Kmat, extp,
                                            w_no, b_no, w_o, b_o, out);
}

// round 7
// speedup vs baseline: 2.5906x; 1.2095x over previous
#include <cuda_runtime.h>

#define NCAMS 6
#define CFEAT 64
#define HH 88
#define WW 160
#define HWSZ (HH*WW)
#define NVOX 200000
#define TILE 32
#define WSTR 68   // padded w_no row stride (16B-aligned rows)

__global__ __launch_bounds__(256) void vox_fusion_kernel(
    const float* __restrict__ feat,    // [6,64,88,160]
    const float* __restrict__ maskp,   // [6,1,88,160]
    const float* __restrict__ Kmat,    // [6,4,4]
    const float* __restrict__ extp,    // [6,4,4]
    const float* __restrict__ w_no,    // [64,65]
    const float* __restrict__ b_no,    // [64]
    const float* __restrict__ w_o,     // [64,130]
    const float* __restrict__ b_o,     // [64]
    float* __restrict__ out)           // [64, 200000]
{
    __shared__ float sE[NCAMS][12];
    __shared__ float sK[NCAMS][9];
    __shared__ unsigned svalid[NCAMS];
    __shared__ float4 scw[NCAMS * TILE];
    __shared__ int4   soff[NCAMS * TILE];
    __shared__ float  svz[NCAMS * TILE];
    __shared__ float  sf1[TILE * 65];
    __shared__ float  sf2[TILE * 65];
    __shared__ float  swno[CFEAT * WSTR];
    __shared__ float  sbno[CFEAT];

    const int t = threadIdx.x;
    const int i = t & 31;
    const int j = t >> 5;
    const int n = blockIdx.x * TILE + i;

    if (t < 72) {
        sE[t / 12][t % 12] = extp[(t / 12) * 16 + (t % 12)];
    } else if (t < 126) {
        int u = t - 72; int cam = u / 9, e = u % 9;
        sK[cam][e] = Kmat[cam * 16 + (e / 3) * 4 + (e % 3)];
    }
    __syncthreads();

    // ---- Phase 0: projection + validity, one thread per (voxel, cam) ----
    if (t < 192) {
        const int cam = t >> 5;
        const int ixv = n % 100;
        const int iyv = (n / 100) % 100;
        const int izv = n / 10000;
        const float px = -50.0f + (float)ixv;
        const float py = -50.0f + (float)iyv;
        const float pz = -15.0f + 1.5f * (float)izv;

        const float* E  = sE[cam];
        const float* Km = sK[cam];
        float vx = fmaf(E[0], px, fmaf(E[1], py, fmaf(E[2],  pz, E[3])));
        float vy = fmaf(E[4], px, fmaf(E[5], py, fmaf(E[6],  pz, E[7])));
        float vz = fmaf(E[8], px, fmaf(E[9], py, fmaf(E[10], pz, E[11])));
        float cx = fmaf(Km[0], vx, fmaf(Km[1], vy, Km[2] * vz));
        float cy = fmaf(Km[3], vx, fmaf(Km[4], vy, Km[5] * vz));
        float cz = fmaf(Km[6], vx, fmaf(Km[7], vy, Km[8] * vz));
        float denom = cz + 1e-8f;
        float pixx = cx / denom;
        float pixy = cy / denom;
        float gx = (pixx / 159.0f - 0.5f) * 2.0f;
        float gy = (pixy / 87.0f  - 0.5f) * 2.0f;
        bool oob = (gx > 1.0f) || (gx < -1.0f) || (gy > 1.0f) || (gy < -1.0f);
        float x = (gx + 1.0f) * 0.5f * 159.0f;
        float y = (gy + 1.0f) * 0.5f * 87.0f;
        float xr = rintf(x), yr = rintf(y);
        float mv = 0.0f;
        if (xr >= 0.0f && xr <= 159.0f && yr >= 0.0f && yr <= 87.0f)
            mv = __ldg(&maskp[cam * HWSZ + (int)yr * WW + (int)xr]);
        bool valid = (mv > 0.5f) && (vz > 0.0f) && (!oob);

        float4 cw4 = make_float4(0.f, 0.f, 0.f, 0.f);
        int4   o4  = make_int4(0, 0, 0, 0);
        float  vzc = 0.0f;
        if (valid) {
            float x0 = floorf(x), y0 = floorf(y);
            float wx1 = x - x0, wx0 = 1.0f - wx1;
            float wy1 = y - y0, wy0 = 1.0f - wy1;
            float xs2[2] = {x0, x0 + 1.0f}, wxa[2] = {wx0, wx1};
            float ys2[2] = {y0, y0 + 1.0f}, wya[2] = {wy0, wy1};
            float cw[4]; int off[4];
            int idx = 0;
#pragma unroll
            for (int a = 0; a < 2; a++) {
#pragma unroll
                for (int b = 0; b < 2; b++) {
                    float xi = xs2[a], yi = ys2[b];
                    bool v = (xi >= 0.0f) && (xi <= 159.0f) && (yi >= 0.0f) && (yi <= 87.0f);
                    float xc = fminf(fmaxf(xi, 0.0f), 159.0f);
                    float yc = fminf(fmaxf(yi, 0.0f), 87.0f);
                    off[idx] = (int)yc * WW + (int)xc;
                    cw[idx]  = wxa[a] * wya[b] * (v ? 1.0f : 0.0f);
                    idx++;
                }
            }
            cw4 = make_float4(cw[0], cw[1], cw[2], cw[3]);
            o4  = make_int4(off[0], off[1], off[2], off[3]);
            vzc = vz * 0.01f;
        }
        unsigned bal = __ballot_sync(0xffffffffu, valid);
        if (i == 0) svalid[cam] = bal;
        scw[t]  = cw4;
        soff[t] = o4;
        svz[t]  = vzc;
    }
    __syncthreads();

    const unsigned g1m = svalid[0] | svalid[3] | svalid[4];
    int cnt = 0;
#pragma unroll
    for (int c = 0; c < NCAMS; c++) cnt += (svalid[c] >> i) & 1;
    const unsigned m1 = __ballot_sync(0xffffffffu, cnt == 1);   // lane == voxel i
    const unsigned m2 = __ballot_sync(0xffffffffu, cnt == 2);

    // ---- Fully-inactive tile: zero out and leave ----
    if ((m1 | m2) == 0u) {
#pragma unroll
        for (int m = 0; m < 8; m++)
            out[(j * 8 + m) * NVOX + n] = 0.0f;
        return;
    }

    // ---- Stage w_no (padded, 16B-aligned rows) only if some voxel has cnt==1.
    //      Overlaps with phase-1 gathers; one sync before phase 2. ----
    if (m1) {
        for (int idx = t; idx < CFEAT * 65; idx += 256) {
            int r = idx / 65, c = idx - r * 65;
            swno[r * WSTR + c] = w_no[idx];
        }
        if (t < CFEAT) sbno[t] = b_no[t];
    }

    // ---- Phase 1: gather for voxels with count 1 or 2 ----
    const bool active = (cnt == 1) || (cnt == 2);
    if (active) {
        float acc1[8], acc2[8];
#pragma unroll
        for (int k = 0; k < 8; k++) { acc1[k] = 0.0f; acc2[k] = 0.0f; }
#pragma unroll
        for (int cam = 0; cam < NCAMS; cam++) {
            if ((svalid[cam] >> i) & 1) {
                float4 w4 = scw[cam * TILE + i];
                int4   o4 = soff[cam * TILE + i];
                const float* base = feat + cam * (CFEAT * HWSZ) + (j * 8) * HWSZ;
                const bool g1 = (cam == 0) || (cam == 3) || (cam == 4);
#pragma unroll
                for (int k = 0; k < 8; k++) {
                    const float* bk = base + k * HWSZ;
                    float v0 = __ldg(bk + o4.x);
                    float v1 = __ldg(bk + o4.y);
                    float v2 = __ldg(bk + o4.z);
                    float v3 = __ldg(bk + o4.w);
                    float val = fmaf(v3, w4.w, fmaf(v2, w4.z, fmaf(v1, w4.y, v0 * w4.x)));
                    if (g1) acc1[k] += val; else acc2[k] += val;
                }
            }
        }
#pragma unroll
        for (int k = 0; k < 8; k++) {
            sf1[i * 65 + j * 8 + k] = acc1[k];
            sf2[i * 65 + j * 8 + k] = acc2[k];
        }
        if (j == 0) {
            sf1[i * 65 + 64] = svz[0 * TILE + i] + svz[3 * TILE + i] + svz[4 * TILE + i];
            sf2[i * 65 + 64] = svz[1 * TILE + i] + svz[2 * TILE + i] + svz[5 * TILE + i];
        }
    }
    __syncthreads();

    // ---- Phase 2: per-voxel linear + ELU ----
    float s[8];
#pragma unroll
    for (int m = 0; m < 8; m++) s[m] = 0.0f;

    if (cnt == 1) {
        // exactly one valid cam -> one group buffer is zero; read only the live one
        const bool useg1 = (g1m >> i) & 1;
        const float* fptr = (useg1 ? sf1 : sf2) + i * 65;
#pragma unroll
        for (int m = 0; m < 8; m++) s[m] = sbno[j * 8 + m];
        const float* wrow = swno + (j * 8) * WSTR;
#pragma unroll 4
        for (int kt = 0; kt < 64; kt += 4) {
            float f0 = fptr[kt], f1 = fptr[kt + 1], f2 = fptr[kt + 2], f3 = fptr[kt + 3];
#pragma unroll
            for (int m = 0; m < 8; m++) {
                float4 w = *(const float4*)(wrow + m * WSTR + kt);
                s[m] = fmaf(w.x, f0, s[m]);
                s[m] = fmaf(w.y, f1, s[m]);
                s[m] = fmaf(w.z, f2, s[m]);
                s[m] = fmaf(w.w, f3, s[m]);
            }
        }
        float f64 = fptr[64];
#pragma unroll
        for (int m = 0; m < 8; m++)
            s[m] = fmaf(wrow[m * WSTR + 64], f64, s[m]);
#pragma unroll
        for (int m = 0; m < 8; m++) s[m] = (s[m] > 0.0f) ? s[m] : expm1f(s[m]);
    } else if (cnt == 2) {
        const float* w = w_o + (j * 8) * 130;
#pragma unroll
        for (int m = 0; m < 8; m++) s[m] = __ldg(&b_o[j * 8 + m]);
        for (int k = 0; k < 65; k++) {
            float f1 = sf1[i * 65 + k];
            float f2 = sf2[i * 65 + k];
#pragma unroll
            for (int m = 0; m < 8; m++) {
                s[m] = fmaf(__ldg(&w[m * 130 + k]), f1, s[m]);
                s[m] = fmaf(__ldg(&w[m * 130 + 65 + k]), f2, s[m]);
            }
        }
#pragma unroll
        for (int m = 0; m < 8; m++) s[m] = (s[m] > 0.0f) ? s[m] : expm1f(s[m]);
    }
#pragma unroll
    for (int m = 0; m < 8; m++)
        out[(j * 8 + m) * NVOX + n] = s[m];
}

extern "C" void kernel_launch(void* const* d_in, const int* in_sizes, int n_in,
                              void* d_out, int out_size) {
    const float* feat  = (const float*)d_in[0];
    const float* maskp = (const float*)d_in[1];
    const float* Kmat  = (const float*)d_in[2];
    const float* extp  = (const float*)d_in[3];
    const float* w_no  = (const float*)d_in[4];
    const float* b_no  = (const float*)d_in[5];
    const float* w_o   = (const float*)d_in[6];
    const float* b_o   = (const float*)d_in[7];
    float* out = (float*)d_out;
    vox_fusion_kernel<<<NVOX / TILE, 256>>>(feat, maskp, Kmat, extp,
                                            w_no, b_no, w_o, b_o, out);
}